// round 3
// baseline (speedup 1.0000x reference)
#include <cuda_runtime.h>
#include <cstdint>

#define EPSBN 1e-3f

// Intermediate y = relu(bn1(conv(x))) : (64, 512, 128) fp32 = 16.8 MB (fits L2)
__device__ float g_y[64 * 512 * 128];

// Packed f32x2 FMA: d.lo += a.lo*b.lo ; d.hi += a.hi*b.hi  (2x fp32 throughput)
__device__ __forceinline__ void ffma2(unsigned long long& d, unsigned long long a,
                                      unsigned long long b) {
    asm("fma.rn.f32x2 %0, %1, %2, %0;" : "+l"(d) : "l"(a), "l"(b));
}
__device__ __forceinline__ unsigned long long dup2(float v) {
    unsigned long long r;
    asm("mov.b64 %0, {%1, %1};" : "=l"(r) : "f"(v));
    return r;
}
__device__ __forceinline__ float lo32(unsigned long long v) {
    return __uint_as_float((unsigned)(v & 0xffffffffu));
}
__device__ __forceinline__ float hi32(unsigned long long v) {
    return __uint_as_float((unsigned)(v >> 32));
}

// ============================================================================
// Stage 1: Conv1D(K=7, SAME) + BN1 + ReLU  -> g_y
// Per (batch b, l-tile 64): C[64 l, 128 f] = A[64, 448] * W[448, 128]
// A[m, k*64+c] = x[b, l0+m+k-3, c]. A stored UN-duplicated; dup in registers.
// 128 thr, 8(l) x 8(f) per thread, f32x2-paired along f. 4 blocks/SM.
// ============================================================================
__global__ __launch_bounds__(128, 4) void conv_bn_kernel(
    const float* __restrict__ x, const float* __restrict__ w,
    const float* __restrict__ cbias,
    const float* __restrict__ g1, const float* __restrict__ b1,
    const float* __restrict__ m1, const float* __restrict__ v1) {
    const int b = blockIdx.y;
    const int l0 = blockIdx.x * 64;

    __shared__ float xs[70 * 64];   // x slice (un-duplicated)
    __shared__ float ws[16 * 128];  // weight K-chunk

    const int tid = threadIdx.x;
    const int tx = tid & 15;  // f-group: f = tx*8 .. tx*8+7
    const int ty = tid >> 4;  // l-group: m = ty*8 .. ty*8+7

    // Load x[b, l0-3 .. l0+66, 0:64]
    const float* xb = x + (size_t)b * 512 * 64;
    for (int idx = tid; idx < 70 * 64; idx += 128) {
        const int i = idx >> 6, c = idx & 63;
        const int row = l0 - 3 + i;
        xs[idx] = (row >= 0 && row < 512) ? xb[row * 64 + c] : 0.0f;
    }

    unsigned long long acc[8][4];
#pragma unroll
    for (int i = 0; i < 8; i++)
#pragma unroll
        for (int p = 0; p < 4; p++) acc[i][p] = 0ull;

    // prefetch W chunk 0 into registers
    float4 wreg[4];
#pragma unroll
    for (int q = 0; q < 4; q++) {
        const int e = q * 512 + tid * 4;
        wreg[q] = *(const float4*)&w[(e >> 7) * 128 + (e & 127)];
    }

    for (int kc = 0; kc < 448; kc += 16) {
        // commit prefetched W chunk to smem
#pragma unroll
        for (int q = 0; q < 4; q++) {
            const int e = q * 512 + tid * 4;
            *(float4*)&ws[e] = wreg[q];
        }
        __syncthreads();
        // prefetch next chunk (overlaps with compute below)
        if (kc + 16 < 448) {
#pragma unroll
            for (int q = 0; q < 4; q++) {
                const int e = q * 512 + tid * 4;
                wreg[q] = *(const float4*)&w[(kc + 16 + (e >> 7)) * 128 + (e & 127)];
            }
        }
        const int k = kc >> 6;       // conv tap (fixed for whole chunk)
        const int cb = kc & 63;      // channel base
        const int abase = (ty * 8 + k) * 64 + cb;
#pragma unroll 4
        for (int kk = 0; kk < 16; kk++) {
            const ulonglong2 w01 = *(const ulonglong2*)&ws[kk * 128 + tx * 8];
            const ulonglong2 w23 = *(const ulonglong2*)&ws[kk * 128 + tx * 8 + 4];
#pragma unroll
            for (int i = 0; i < 8; i++) {
                const unsigned long long da = dup2(xs[abase + i * 64 + kk]);
                ffma2(acc[i][0], da, w01.x);
                ffma2(acc[i][1], da, w01.y);
                ffma2(acc[i][2], da, w23.x);
                ffma2(acc[i][3], da, w23.y);
            }
        }
        __syncthreads();
    }

    // Epilogue: bias + BN1 + ReLU
#pragma unroll
    for (int p = 0; p < 4; p++) {
        const int f0 = tx * 8 + 2 * p;
        const float s0 = g1[f0] * rsqrtf(v1[f0] + EPSBN);
        const float s1 = g1[f0 + 1] * rsqrtf(v1[f0 + 1] + EPSBN);
        const float sh0 = (cbias[f0] - m1[f0]) * s0 + b1[f0];
        const float sh1 = (cbias[f0 + 1] - m1[f0 + 1]) * s1 + b1[f0 + 1];
#pragma unroll
        for (int i = 0; i < 8; i++) {
            const int l = l0 + ty * 8 + i;
            float2 r;
            r.x = fmaxf(fmaf(lo32(acc[i][p]), s0, sh0), 0.0f);
            r.y = fmaxf(fmaf(hi32(acc[i][p]), s1, sh1), 0.0f);
            *(float2*)&g_y[(size_t)b * 65536 + l * 128 + f0] = r;
        }
    }
}

// ============================================================================
// Stage 2: LocallyConnected1D(K=7, VALID) + BN2 + ReLU
// Per l (506 blocks): C[64 b, 128 f] = P[64, 896] * Wl[896, 128]
// P row b contiguous at g_y + b*65536 + l*128. pd stored UN-duplicated,
// padded to 68/row for conflict-free vec reads; dup in registers.
// ============================================================================
__global__ __launch_bounds__(128, 4) void local_bn_kernel(
    const float* __restrict__ lw, const float* __restrict__ lb,
    const float* __restrict__ g2, const float* __restrict__ b2,
    const float* __restrict__ m2, const float* __restrict__ v2,
    float* __restrict__ out) {
    const int l = blockIdx.x;

    __shared__ float ws[16 * 128];  // weight K-chunk
    __shared__ float pd[16 * 68];   // patch K-chunk: pd[kk][batch], pad 68

    const int tid = threadIdx.x;
    const int tx = tid & 15;  // f-group
    const int ty = tid >> 4;  // batch-group: m = ty*8 .. ty*8+7

    const float* Wb = lw + (size_t)l * 896 * 128;
    const int pb = tid >> 1, ph = tid & 1;  // this thread loads batch pb, k-rows ph*8..+7
    const float* Prow = g_y + (size_t)pb * 65536 + l * 128 + ph * 8;

    unsigned long long acc[8][4];
#pragma unroll
    for (int i = 0; i < 8; i++)
#pragma unroll
        for (int p = 0; p < 4; p++) acc[i][p] = 0ull;

    // prefetch chunk 0
    float4 wreg[4], areg0, areg1;
#pragma unroll
    for (int q = 0; q < 4; q++) {
        const int e = q * 512 + tid * 4;
        wreg[q] = *(const float4*)&Wb[(e >> 7) * 128 + (e & 127)];
    }
    areg0 = *(const float4*)&Prow[0];
    areg1 = *(const float4*)&Prow[4];

    for (int kc = 0; kc < 896; kc += 16) {
        // commit prefetched chunk to smem
#pragma unroll
        for (int q = 0; q < 4; q++) {
            const int e = q * 512 + tid * 4;
            *(float4*)&ws[e] = wreg[q];
        }
        {
            const int r0 = ph * 8;
            pd[(r0 + 0) * 68 + pb] = areg0.x;
            pd[(r0 + 1) * 68 + pb] = areg0.y;
            pd[(r0 + 2) * 68 + pb] = areg0.z;
            pd[(r0 + 3) * 68 + pb] = areg0.w;
            pd[(r0 + 4) * 68 + pb] = areg1.x;
            pd[(r0 + 5) * 68 + pb] = areg1.y;
            pd[(r0 + 6) * 68 + pb] = areg1.z;
            pd[(r0 + 7) * 68 + pb] = areg1.w;
        }
        __syncthreads();
        // prefetch next chunk (overlaps compute)
        if (kc + 16 < 896) {
#pragma unroll
            for (int q = 0; q < 4; q++) {
                const int e = q * 512 + tid * 4;
                wreg[q] = *(const float4*)&Wb[(kc + 16 + (e >> 7)) * 128 + (e & 127)];
            }
            areg0 = *(const float4*)&Prow[kc + 16];
            areg1 = *(const float4*)&Prow[kc + 20];
        }
#pragma unroll 4
        for (int kk = 0; kk < 16; kk++) {
            const ulonglong2 w01 = *(const ulonglong2*)&ws[kk * 128 + tx * 8];
            const ulonglong2 w23 = *(const ulonglong2*)&ws[kk * 128 + tx * 8 + 4];
            const float4 a0 = *(const float4*)&pd[kk * 68 + ty * 8];
            const float4 a1 = *(const float4*)&pd[kk * 68 + ty * 8 + 4];
            const float av[8] = {a0.x, a0.y, a0.z, a0.w, a1.x, a1.y, a1.z, a1.w};
#pragma unroll
            for (int i = 0; i < 8; i++) {
                const unsigned long long da = dup2(av[i]);
                ffma2(acc[i][0], da, w01.x);
                ffma2(acc[i][1], da, w01.y);
                ffma2(acc[i][2], da, w23.x);
                ffma2(acc[i][3], da, w23.y);
            }
        }
        __syncthreads();
    }

    // Epilogue: local bias + BN2 + ReLU
#pragma unroll
    for (int p = 0; p < 4; p++) {
        const int f0 = tx * 8 + 2 * p;
        const float s0 = g2[f0] * rsqrtf(v2[f0] + EPSBN);
        const float s1 = g2[f0 + 1] * rsqrtf(v2[f0 + 1] + EPSBN);
        const float sh0 = (lb[l * 128 + f0] - m2[f0]) * s0 + b2[f0];
        const float sh1 = (lb[l * 128 + f0 + 1] - m2[f0 + 1]) * s1 + b2[f0 + 1];
#pragma unroll
        for (int i = 0; i < 8; i++) {
            const int bat = ty * 8 + i;
            float2 r;
            r.x = fmaxf(fmaf(lo32(acc[i][p]), s0, sh0), 0.0f);
            r.y = fmaxf(fmaf(hi32(acc[i][p]), s1, sh1), 0.0f);
            *(float2*)&out[(size_t)bat * 506 * 128 + l * 128 + f0] = r;
        }
    }
}

extern "C" void kernel_launch(void* const* d_in, const int* in_sizes, int n_in,
                              void* d_out, int out_size) {
    const float* x      = (const float*)d_in[0];
    const float* conv_w = (const float*)d_in[1];
    const float* conv_b = (const float*)d_in[2];
    const float* g1     = (const float*)d_in[3];
    const float* b1     = (const float*)d_in[4];
    const float* m1     = (const float*)d_in[5];
    const float* v1     = (const float*)d_in[6];
    const float* lw     = (const float*)d_in[7];
    const float* lb     = (const float*)d_in[8];
    const float* g2     = (const float*)d_in[9];
    const float* b2     = (const float*)d_in[10];
    const float* m2     = (const float*)d_in[11];
    const float* v2     = (const float*)d_in[12];
    float* out = (float*)d_out;

    conv_bn_kernel<<<dim3(8, 64), 128>>>(x, conv_w, conv_b, g1, b1, m1, v1);
    local_bn_kernel<<<506, 128>>>(lw, lb, g2, b2, m2, v2, out);
}

// round 5
// speedup vs baseline: 1.4924x; 1.4924x over previous
#include <cuda_runtime.h>
#include <cstdint>

#define EPSBN 1e-3f
#define APITCH 36
#define PLANE (64 * APITCH)

// tf32-bit-pattern activations (hi + residual planes)
__device__ uint32_t g_xh[64 * 512 * 64];
__device__ uint32_t g_xl[64 * 512 * 64];
__device__ uint32_t g_yh[64 * 512 * 128];
__device__ uint32_t g_yl[64 * 512 * 128];

__device__ __forceinline__ uint32_t f2tf(float f) {
    uint32_t r; asm("cvt.rna.tf32.f32 %0, %1;" : "=r"(r) : "f"(f)); return r;
}
__device__ __forceinline__ uint32_t s2u(const void* p) {
    uint32_t a;
    asm("{ .reg .u64 t; cvta.to.shared.u64 t, %1; cvt.u32.u64 %0, t; }" : "=r"(a) : "l"(p));
    return a;
}
__device__ __forceinline__ void cpa16(uint32_t d, const void* s, uint32_t sz) {
    asm volatile("cp.async.cg.shared.global [%0], [%1], 16, %2;"
                 :: "r"(d), "l"(s), "r"(sz) : "memory");
}
__device__ __forceinline__ void cpcommit() { asm volatile("cp.async.commit_group;" ::: "memory"); }
template <int N> __device__ __forceinline__ void cpwait() {
    asm volatile("cp.async.wait_group %0;" :: "n"(N) : "memory");
}
// m16n8k8 tf32 MMA (sm_80+ baseline PTX -> HMMA on sm_103)
__device__ __forceinline__ void mma8(float* d, const uint32_t* a, const uint32_t* b) {
    asm volatile(
        "mma.sync.aligned.m16n8k8.row.col.f32.tf32.tf32.f32 "
        "{%0,%1,%2,%3}, {%4,%5,%6,%7}, {%8,%9}, {%0,%1,%2,%3};"
        : "+f"(d[0]), "+f"(d[1]), "+f"(d[2]), "+f"(d[3])
        : "r"(a[0]), "r"(a[1]), "r"(a[2]), "r"(a[3]), "r"(b[0]), "r"(b[1]));
}

// ============================================================================
// Shared GEMM core: D[64 m, 128 f] = (Ah + Al)[64, K] * tf32(W)[K, 128]
// A planes are tf32-bit uint32 arrays; row m starts at off0 + m*mstride,
// contiguous along k. CHK: zero-fill rows outside [0, 32768) (conv padding).
// Warp w owns f-slice [w*16, w*16+16), all 64 m. k32 chunks, cp.async 2-buf.
// ============================================================================
template <int NC, bool CHK>
__device__ __forceinline__ void gemm_core(
    uint32_t (&As)[2][2][PLANE], const float* __restrict__ W,
    const uint32_t* __restrict__ Ah, const uint32_t* __restrict__ Al,
    int off0, int mstride, float acc[4][2][4], int tid) {
    const int w = tid >> 5, lane = tid & 31;
    const int gp = lane >> 2, tg = lane & 3;
    const uint32_t smb = s2u(&As[0][0][0]);

    auto stage = [&](int c, int buf) {
        const int kc = c * 32;
#pragma unroll
        for (int q = 0; q < 2; q++) {
            const int idx4 = tid + 256 * q;
            const int m = idx4 >> 3, c4 = idx4 & 7;
            const int so = off0 + m * mstride + kc + c4 * 4;
            const bool ok = !CHK || ((unsigned)so < 32768u);
            const int soc = ok ? so : 0;
            const uint32_t d =
                smb + (uint32_t)(buf * 2 * PLANE + m * APITCH + c4 * 4) * 4u;
            cpa16(d, Ah + soc, ok ? 16u : 0u);
            cpa16(d + PLANE * 4u, Al + soc, ok ? 16u : 0u);
        }
        cpcommit();
    };

    stage(0, 0);
    for (int c = 0; c < NC; c++) {
        const int buf = c & 1;
        if (c + 1 < NC) { stage(c + 1, buf ^ 1); cpwait<1>(); }
        else            { cpwait<0>(); }
        __syncthreads();
        const uint32_t* __restrict__ smH = &As[buf][0][0];
        const uint32_t* __restrict__ smL = &As[buf][1][0];
#pragma unroll
        for (int s = 0; s < 4; s++) {
            const int kg = c * 32 + s * 8;
            // B fragments straight from global fp32 -> tf32 (single pass)
            const float* wp = W + (size_t)(kg + tg) * 128 + w * 16 + gp;
            uint32_t b[4];
            b[0] = f2tf(wp[0]);    // nt0: k=tg,   n=gp
            b[1] = f2tf(wp[512]);  // nt0: k=tg+4
            b[2] = f2tf(wp[8]);    // nt1
            b[3] = f2tf(wp[520]);
            const int col = s * 8 + tg;
#pragma unroll
            for (int mt = 0; mt < 4; mt++) {
                const int r = mt * 16 + gp;
                uint32_t a[4];
                a[0] = smH[r * APITCH + col];
                a[1] = smH[(r + 8) * APITCH + col];
                a[2] = smH[r * APITCH + col + 4];
                a[3] = smH[(r + 8) * APITCH + col + 4];
                mma8(acc[mt][0], a, b);
                mma8(acc[mt][1], a, b + 2);
                a[0] = smL[r * APITCH + col];
                a[1] = smL[(r + 8) * APITCH + col];
                a[2] = smL[r * APITCH + col + 4];
                a[3] = smL[(r + 8) * APITCH + col + 4];
                mma8(acc[mt][0], a, b);
                mma8(acc[mt][1], a, b + 2);
            }
        }
        __syncthreads();
    }
}

// ---------------- split x into tf32 hi/lo planes ----------------
__global__ __launch_bounds__(256) void split_x_kernel(const float* __restrict__ x) {
    const int i = (blockIdx.x * 256 + threadIdx.x) * 4;
    const float4 v = *(const float4*)&x[i];
    uint4 h;
    h.x = f2tf(v.x); h.y = f2tf(v.y); h.z = f2tf(v.z); h.w = f2tf(v.w);
    uint4 lo;
    lo.x = f2tf(v.x - __uint_as_float(h.x));
    lo.y = f2tf(v.y - __uint_as_float(h.y));
    lo.z = f2tf(v.z - __uint_as_float(h.z));
    lo.w = f2tf(v.w - __uint_as_float(h.w));
    *(uint4*)&g_xh[i] = h;
    *(uint4*)&g_xl[i] = lo;
}

// ---------------- Stage 1: Conv1D(SAME) + BN1 + ReLU -> g_yh/g_yl ----------------
__global__ __launch_bounds__(256, 2) void conv_tc(
    const float* __restrict__ w, const float* __restrict__ cb,
    const float* __restrict__ g1, const float* __restrict__ b1,
    const float* __restrict__ m1, const float* __restrict__ v1) {
    __shared__ uint32_t As[2][2][PLANE];
    const int tid = threadIdx.x;
    const int b = blockIdx.y, l0 = blockIdx.x * 64;
    float acc[4][2][4] = {};
    gemm_core<14, true>(As, w, g_xh + b * 32768, g_xl + b * 32768,
                        (l0 - 3) * 64, 64, acc, tid);
    const int wid = tid >> 5, lane = tid & 31, gp = lane >> 2, tg = lane & 3;
#pragma unroll
    for (int nt = 0; nt < 2; nt++) {
        const int f = wid * 16 + nt * 8 + tg * 2;
        const float s0 = g1[f] * rsqrtf(v1[f] + EPSBN);
        const float s1 = g1[f + 1] * rsqrtf(v1[f + 1] + EPSBN);
        const float h0 = (cb[f] - m1[f]) * s0 + b1[f];
        const float h1 = (cb[f + 1] - m1[f + 1]) * s1 + b1[f + 1];
#pragma unroll
        for (int mt = 0; mt < 4; mt++) {
#pragma unroll
            for (int hr = 0; hr < 2; hr++) {
                const int l = l0 + mt * 16 + gp + hr * 8;
                const float y0 = fmaxf(fmaf(acc[mt][nt][hr * 2], s0, h0), 0.f);
                const float y1 = fmaxf(fmaf(acc[mt][nt][hr * 2 + 1], s1, h1), 0.f);
                const uint32_t yh0 = f2tf(y0), yh1 = f2tf(y1);
                const size_t o = (size_t)b * 65536 + (size_t)l * 128 + f;
                *(uint2*)&g_yh[o] = make_uint2(yh0, yh1);
                *(uint2*)&g_yl[o] = make_uint2(f2tf(y0 - __uint_as_float(yh0)),
                                               f2tf(y1 - __uint_as_float(yh1)));
            }
        }
    }
}

// ---------------- Stage 2: LocallyConnected1D(VALID) + BN2 + ReLU ----------------
__global__ __launch_bounds__(256, 2) void local_tc(
    const float* __restrict__ lw, const float* __restrict__ lb,
    const float* __restrict__ g2, const float* __restrict__ b2,
    const float* __restrict__ m2, const float* __restrict__ v2,
    float* __restrict__ out) {
    __shared__ uint32_t As[2][2][PLANE];
    const int tid = threadIdx.x;
    const int l = blockIdx.x;
    float acc[4][2][4] = {};
    gemm_core<28, false>(As, lw + (size_t)l * 896 * 128, g_yh, g_yl,
                         l * 128, 65536, acc, tid);
    const int wid = tid >> 5, lane = tid & 31, gp = lane >> 2, tg = lane & 3;
#pragma unroll
    for (int nt = 0; nt < 2; nt++) {
        const int f = wid * 16 + nt * 8 + tg * 2;
        const float s0 = g2[f] * rsqrtf(v2[f] + EPSBN);
        const float s1 = g2[f + 1] * rsqrtf(v2[f + 1] + EPSBN);
        const float h0 = (lb[l * 128 + f] - m2[f]) * s0 + b2[f];
        const float h1 = (lb[l * 128 + f + 1] - m2[f + 1]) * s1 + b2[f + 1];
#pragma unroll
        for (int mt = 0; mt < 4; mt++) {
#pragma unroll
            for (int hr = 0; hr < 2; hr++) {
                const int bat = mt * 16 + gp + hr * 8;
                float2 r;
                r.x = fmaxf(fmaf(acc[mt][nt][hr * 2], s0, h0), 0.f);
                r.y = fmaxf(fmaf(acc[mt][nt][hr * 2 + 1], s1, h1), 0.f);
                *(float2*)&out[(size_t)bat * 506 * 128 + (size_t)l * 128 + f] = r;
            }
        }
    }
}

extern "C" void kernel_launch(void* const* d_in, const int* in_sizes, int n_in,
                              void* d_out, int out_size) {
    const float* x      = (const float*)d_in[0];
    const float* conv_w = (const float*)d_in[1];
    const float* conv_b = (const float*)d_in[2];
    const float* g1     = (const float*)d_in[3];
    const float* b1     = (const float*)d_in[4];
    const float* m1     = (const float*)d_in[5];
    const float* v1     = (const float*)d_in[6];
    const float* lw     = (const float*)d_in[7];
    const float* lb     = (const float*)d_in[8];
    const float* g2     = (const float*)d_in[9];
    const float* b2     = (const float*)d_in[10];
    const float* m2     = (const float*)d_in[11];
    const float* v2     = (const float*)d_in[12];
    float* out = (float*)d_out;

    split_x_kernel<<<2048, 256>>>(x);
    conv_tc<<<dim3(8, 64), 256>>>(conv_w, conv_b, g1, b1, m1, v1);
    local_tc<<<506, 256>>>(lw, lb, g2, b2, m2, v2, out);
}

// round 6
// speedup vs baseline: 2.5211x; 1.6893x over previous
#include <cuda_runtime.h>
#include <cstdint>

#define EPSBN 1e-3f
#define APITCH 36
#define PLANE (64 * APITCH)

// tf32-bit-pattern activations
__device__ uint32_t g_xh[64 * 512 * 64];
__device__ uint32_t g_xl[64 * 512 * 64];
__device__ uint32_t g_yh[64 * 512 * 128];

__device__ __forceinline__ uint32_t f2tf(float f) {
    uint32_t r; asm("cvt.rna.tf32.f32 %0, %1;" : "=r"(r) : "f"(f)); return r;
}
__device__ __forceinline__ uint32_t s2u(const void* p) {
    uint32_t a;
    asm("{ .reg .u64 t; cvta.to.shared.u64 t, %1; cvt.u32.u64 %0, t; }" : "=r"(a) : "l"(p));
    return a;
}
__device__ __forceinline__ void cpa16(uint32_t d, const void* s, uint32_t sz) {
    asm volatile("cp.async.cg.shared.global [%0], [%1], 16, %2;"
                 :: "r"(d), "l"(s), "r"(sz) : "memory");
}
__device__ __forceinline__ void cpcommit() { asm volatile("cp.async.commit_group;" ::: "memory"); }
template <int N> __device__ __forceinline__ void cpwait() {
    asm volatile("cp.async.wait_group %0;" :: "n"(N) : "memory");
}
__device__ __forceinline__ void mma8(float* d, const uint32_t* a, const uint32_t* b) {
    asm volatile(
        "mma.sync.aligned.m16n8k8.row.col.f32.tf32.tf32.f32 "
        "{%0,%1,%2,%3}, {%4,%5,%6,%7}, {%8,%9}, {%0,%1,%2,%3};"
        : "+f"(d[0]), "+f"(d[1]), "+f"(d[2]), "+f"(d[3])
        : "r"(a[0]), "r"(a[1]), "r"(a[2]), "r"(a[3]), "r"(b[0]), "r"(b[1]));
}

// ============================================================================
// GEMM core: D[64 m, 128 f] = A[64, K] * tf32(W)[K, 128]
// 128 threads = 4 warps; warp w owns f in [w*32, w*32+32) (nt=4).
// A planes: tf32-bit uint32, row m at off0 + m*mstride, contiguous along k.
// PLANES=2 adds the residual plane (Al). CHK: zero-fill rows outside x (SAME pad).
// ============================================================================
template <int NC, int PLANES, bool CHK>
__device__ __forceinline__ void gemm_core(
    uint32_t* As,  // [2][PLANES][PLANE]
    const float* __restrict__ W,
    const uint32_t* __restrict__ Ah, const uint32_t* __restrict__ Al,
    int off0, int mstride, float acc[4][4][4], int tid) {
    const int w = tid >> 5, lane = tid & 31;
    const int gp = lane >> 2, tg = lane & 3;
    const uint32_t smb = s2u(As);
    const int BUFSTRIDE = PLANES * PLANE;

    auto stage = [&](int c, int buf) {
        const int kc = c * 32;
#pragma unroll
        for (int q = 0; q < 4; q++) {
            const int idx4 = tid + 128 * q;  // 512 x 16B per plane
            const int m = idx4 >> 3, c4 = idx4 & 7;
            const int so = off0 + m * mstride + kc + c4 * 4;
            const bool ok = !CHK || ((unsigned)so < 32768u);
            const int soc = ok ? so : 0;
            const uint32_t d =
                smb + (uint32_t)(buf * BUFSTRIDE + m * APITCH + c4 * 4) * 4u;
            cpa16(d, Ah + soc, ok ? 16u : 0u);
            if (PLANES == 2) cpa16(d + PLANE * 4u, Al + soc, ok ? 16u : 0u);
        }
        cpcommit();
    };

    stage(0, 0);
    for (int c = 0; c < NC; c++) {
        const int buf = c & 1;
        if (c + 1 < NC) { stage(c + 1, buf ^ 1); cpwait<1>(); }
        else            { cpwait<0>(); }
        __syncthreads();
        const uint32_t* __restrict__ smH = As + buf * BUFSTRIDE;
        const uint32_t* __restrict__ smL = smH + PLANE;
#pragma unroll
        for (int s = 0; s < 4; s++) {
            const int kg = c * 32 + s * 8;
            const float* wp = W + (size_t)(kg + tg) * 128 + w * 32 + gp;
            uint32_t b[8];
#pragma unroll
            for (int nt = 0; nt < 4; nt++) {
                b[2 * nt]     = f2tf(__ldcs(wp + nt * 8));
                b[2 * nt + 1] = f2tf(__ldcs(wp + nt * 8 + 512));
            }
            const int col = s * 8 + tg;
#pragma unroll
            for (int mt = 0; mt < 4; mt++) {
                const int r = mt * 16 + gp;
                uint32_t a[4];
                a[0] = smH[r * APITCH + col];
                a[1] = smH[(r + 8) * APITCH + col];
                a[2] = smH[r * APITCH + col + 4];
                a[3] = smH[(r + 8) * APITCH + col + 4];
#pragma unroll
                for (int nt = 0; nt < 4; nt++) mma8(acc[mt][nt], a, b + 2 * nt);
                if (PLANES == 2) {
                    a[0] = smL[r * APITCH + col];
                    a[1] = smL[(r + 8) * APITCH + col];
                    a[2] = smL[r * APITCH + col + 4];
                    a[3] = smL[(r + 8) * APITCH + col + 4];
#pragma unroll
                    for (int nt = 0; nt < 4; nt++) mma8(acc[mt][nt], a, b + 2 * nt);
                }
            }
        }
        __syncthreads();
    }
}

// ---------------- split x into tf32 hi/lo planes ----------------
__global__ __launch_bounds__(256) void split_x_kernel(const float* __restrict__ x) {
    const int i = (blockIdx.x * 256 + threadIdx.x) * 4;
    const float4 v = *(const float4*)&x[i];
    uint4 h;
    h.x = f2tf(v.x); h.y = f2tf(v.y); h.z = f2tf(v.z); h.w = f2tf(v.w);
    uint4 lo;
    lo.x = f2tf(v.x - __uint_as_float(h.x));
    lo.y = f2tf(v.y - __uint_as_float(h.y));
    lo.z = f2tf(v.z - __uint_as_float(h.z));
    lo.w = f2tf(v.w - __uint_as_float(h.w));
    *(uint4*)&g_xh[i] = h;
    *(uint4*)&g_xl[i] = lo;
}

// ---------------- Stage 1: Conv1D(SAME) + BN1 + ReLU -> g_yh ----------------
__global__ __launch_bounds__(128, 4) void conv_tc(
    const float* __restrict__ w, const float* __restrict__ cb,
    const float* __restrict__ g1, const float* __restrict__ b1,
    const float* __restrict__ m1, const float* __restrict__ v1) {
    __shared__ uint32_t As[2 * 2 * PLANE];
    const int tid = threadIdx.x;
    const int b = blockIdx.y, l0 = blockIdx.x * 64;
    float acc[4][4][4] = {};
    gemm_core<14, 2, true>(As, w, g_xh + b * 32768, g_xl + b * 32768,
                           (l0 - 3) * 64, 64, acc, tid);
    const int wid = tid >> 5, lane = tid & 31, gp = lane >> 2, tg = lane & 3;
#pragma unroll
    for (int nt = 0; nt < 4; nt++) {
        const int f = wid * 32 + nt * 8 + tg * 2;
        const float s0 = g1[f] * rsqrtf(v1[f] + EPSBN);
        const float s1 = g1[f + 1] * rsqrtf(v1[f + 1] + EPSBN);
        const float h0 = (cb[f] - m1[f]) * s0 + b1[f];
        const float h1 = (cb[f + 1] - m1[f + 1]) * s1 + b1[f + 1];
#pragma unroll
        for (int mt = 0; mt < 4; mt++) {
#pragma unroll
            for (int hr = 0; hr < 2; hr++) {
                const int l = l0 + mt * 16 + gp + hr * 8;
                const float y0 = fmaxf(fmaf(acc[mt][nt][hr * 2], s0, h0), 0.f);
                const float y1 = fmaxf(fmaf(acc[mt][nt][hr * 2 + 1], s1, h1), 0.f);
                *(uint2*)&g_yh[(size_t)b * 65536 + (size_t)l * 128 + f] =
                    make_uint2(f2tf(y0), f2tf(y1));
            }
        }
    }
}

// ---------------- Stage 2: LocallyConnected1D(VALID) + BN2 + ReLU ----------------
__global__ __launch_bounds__(128, 4) void local_tc(
    const float* __restrict__ lw, const float* __restrict__ lb,
    const float* __restrict__ g2, const float* __restrict__ b2,
    const float* __restrict__ m2, const float* __restrict__ v2,
    float* __restrict__ out) {
    __shared__ uint32_t As[2 * 1 * PLANE];
    const int tid = threadIdx.x;
    const int l = blockIdx.x;
    float acc[4][4][4] = {};
    gemm_core<28, 1, false>(As, lw + (size_t)l * 896 * 128, g_yh, g_yh,
                            l * 128, 65536, acc, tid);
    const int wid = tid >> 5, lane = tid & 31, gp = lane >> 2, tg = lane & 3;
#pragma unroll
    for (int nt = 0; nt < 4; nt++) {
        const int f = wid * 32 + nt * 8 + tg * 2;
        const float s0 = g2[f] * rsqrtf(v2[f] + EPSBN);
        const float s1 = g2[f + 1] * rsqrtf(v2[f + 1] + EPSBN);
        const float h0 = (lb[l * 128 + f] - m2[f]) * s0 + b2[f];
        const float h1 = (lb[l * 128 + f + 1] - m2[f + 1]) * s1 + b2[f + 1];
#pragma unroll
        for (int mt = 0; mt < 4; mt++) {
#pragma unroll
            for (int hr = 0; hr < 2; hr++) {
                const int bat = mt * 16 + gp + hr * 8;
                float2 r;
                r.x = fmaxf(fmaf(acc[mt][nt][hr * 2], s0, h0), 0.f);
                r.y = fmaxf(fmaf(acc[mt][nt][hr * 2 + 1], s1, h1), 0.f);
                *(float2*)&out[(size_t)bat * 506 * 128 + (size_t)l * 128 + f] = r;
            }
        }
    }
}

extern "C" void kernel_launch(void* const* d_in, const int* in_sizes, int n_in,
                              void* d_out, int out_size) {
    const float* x      = (const float*)d_in[0];
    const float* conv_w = (const float*)d_in[1];
    const float* conv_b = (const float*)d_in[2];
    const float* g1     = (const float*)d_in[3];
    const float* b1     = (const float*)d_in[4];
    const float* m1     = (const float*)d_in[5];
    const float* v1     = (const float*)d_in[6];
    const float* lw     = (const float*)d_in[7];
    const float* lb     = (const float*)d_in[8];
    const float* g2     = (const float*)d_in[9];
    const float* b2     = (const float*)d_in[10];
    const float* m2     = (const float*)d_in[11];
    const float* v2     = (const float*)d_in[12];
    float* out = (float*)d_out;

    split_x_kernel<<<2048, 256>>>(x);
    conv_tc<<<dim3(8, 64), 128>>>(conv_w, conv_b, g1, b1, m1, v1);
    local_tc<<<506, 128>>>(lw, lb, g2, b2, m2, v2, out);
}

// round 7
// speedup vs baseline: 3.2545x; 1.2909x over previous
#include <cuda_runtime.h>
#include <cstdint>

#define EPSBN 1e-3f
#define APITCH 36
#define PLANE (64 * APITCH)        // 2304 words
#define WPITCH 132
#define WWORDS (32 * WPITCH)       // 4224 words
#define BUFW (PLANE + WWORDS)      // per-buffer words (PLANES=1)
#define DYNB (2 * BUFW * 4)        // 52224 bytes

// tf32-bit-pattern activations
__device__ uint32_t g_xh[64 * 512 * 64];
__device__ uint32_t g_yh[64 * 512 * 128];

__device__ __forceinline__ uint32_t f2tf(float f) {
    uint32_t r; asm("cvt.rna.tf32.f32 %0, %1;" : "=r"(r) : "f"(f)); return r;
}
__device__ __forceinline__ uint32_t s2u(const void* p) {
    uint32_t a;
    asm("{ .reg .u64 t; cvta.to.shared.u64 t, %1; cvt.u32.u64 %0, t; }" : "=r"(a) : "l"(p));
    return a;
}
__device__ __forceinline__ void cpa16(uint32_t d, const void* s, uint32_t sz) {
    asm volatile("cp.async.cg.shared.global [%0], [%1], 16, %2;"
                 :: "r"(d), "l"(s), "r"(sz) : "memory");
}
__device__ __forceinline__ void cpcommit() { asm volatile("cp.async.commit_group;" ::: "memory"); }
template <int N> __device__ __forceinline__ void cpwait() {
    asm volatile("cp.async.wait_group %0;" :: "n"(N) : "memory");
}
__device__ __forceinline__ void mma8(float* d, const uint32_t* a, const uint32_t* b) {
    asm volatile(
        "mma.sync.aligned.m16n8k8.row.col.f32.tf32.tf32.f32 "
        "{%0,%1,%2,%3}, {%4,%5,%6,%7}, {%8,%9}, {%0,%1,%2,%3};"
        : "+f"(d[0]), "+f"(d[1]), "+f"(d[2]), "+f"(d[3])
        : "r"(a[0]), "r"(a[1]), "r"(a[2]), "r"(a[3]), "r"(b[0]), "r"(b[1]));
}

// ============================================================================
// GEMM core: D[64 m, 128 f] = A[64, K] * tf32(W)[K, 128]
// 128 threads = 4 warps; warp w owns f in [w*32, w*32+32) (nt=4).
// A: tf32-bit uint32, row m at off0 + m*mstride, contiguous along k.
// W: fp32 row-major [K][128], staged through smem (pitch 132) via cp.async,
// double-buffered with A -> full-chunk (k32) DRAM prefetch distance.
// CHK: zero-fill A rows outside x (conv SAME padding).
// ============================================================================
template <int NC, bool CHK>
__device__ __forceinline__ void gemm_core(
    uint32_t* As, const float* __restrict__ W, const uint32_t* __restrict__ Ah,
    int off0, int mstride, float acc[4][4][4], int tid) {
    const int w = tid >> 5, lane = tid & 31;
    const int gp = lane >> 2, tg = lane & 3;
    const uint32_t smb = s2u(As);

    auto stage = [&](int c, int buf) {
        const int kc = c * 32;
        const uint32_t bb = smb + (uint32_t)(buf * BUFW) * 4u;
        // A: 8 KB -> 4 cpa/thread
#pragma unroll
        for (int q = 0; q < 4; q++) {
            const int idx4 = tid + 128 * q;
            const int m = idx4 >> 3, c4 = idx4 & 7;
            const int so = off0 + m * mstride + kc + c4 * 4;
            const bool ok = !CHK || ((unsigned)so < 32768u);
            cpa16(bb + (uint32_t)(m * APITCH + c4 * 4) * 4u, Ah + (ok ? so : 0),
                  ok ? 16u : 0u);
        }
        // W: 16 KB -> 8 cpa/thread (rows kc..kc+31, pitch 132 in smem)
        const uint32_t wb = bb + (uint32_t)PLANE * 4u;
#pragma unroll
        for (int q = 0; q < 8; q++) {
            const int idx = tid + 128 * q;
            const int row = idx >> 5, c4 = idx & 31;
            cpa16(wb + (uint32_t)(row * WPITCH + c4 * 4) * 4u,
                  W + (size_t)(kc + row) * 128 + c4 * 4, 16u);
        }
        cpcommit();
    };

    stage(0, 0);
    for (int c = 0; c < NC; c++) {
        const int buf = c & 1;
        if (c + 1 < NC) { stage(c + 1, buf ^ 1); cpwait<1>(); }
        else            { cpwait<0>(); }
        __syncthreads();
        const uint32_t* __restrict__ smA = As + buf * BUFW;
        const float* __restrict__ smW = (const float*)(smA + PLANE);
#pragma unroll
        for (int s = 0; s < 4; s++) {
            const int wcol = w * 32 + gp;
            const float* wp0 = smW + (s * 8 + tg) * WPITCH + wcol;
            const float* wp1 = wp0 + 4 * WPITCH;
            uint32_t b[8];
#pragma unroll
            for (int nt = 0; nt < 4; nt++) {
                b[2 * nt]     = f2tf(wp0[nt * 8]);
                b[2 * nt + 1] = f2tf(wp1[nt * 8]);
            }
            const int col = s * 8 + tg;
#pragma unroll
            for (int mt = 0; mt < 4; mt++) {
                const int r = mt * 16 + gp;
                uint32_t a[4];
                a[0] = smA[r * APITCH + col];
                a[1] = smA[(r + 8) * APITCH + col];
                a[2] = smA[r * APITCH + col + 4];
                a[3] = smA[(r + 8) * APITCH + col + 4];
#pragma unroll
                for (int nt = 0; nt < 4; nt++) mma8(acc[mt][nt], a, b + 2 * nt);
            }
        }
        __syncthreads();
    }
}

// ---------------- x -> tf32 hi plane ----------------
__global__ __launch_bounds__(256) void split_x_kernel(const float* __restrict__ x) {
    const int i = (blockIdx.x * 256 + threadIdx.x) * 4;
    const float4 v = *(const float4*)&x[i];
    *(uint4*)&g_xh[i] = make_uint4(f2tf(v.x), f2tf(v.y), f2tf(v.z), f2tf(v.w));
}

// ---------------- Stage 1: Conv1D(SAME) + BN1 + ReLU -> g_yh ----------------
__global__ __launch_bounds__(128, 4) void conv_tc(
    const float* __restrict__ w, const float* __restrict__ cb,
    const float* __restrict__ g1, const float* __restrict__ b1,
    const float* __restrict__ m1, const float* __restrict__ v1) {
    extern __shared__ uint32_t As[];
    const int tid = threadIdx.x;
    const int b = blockIdx.y, l0 = blockIdx.x * 64;
    float acc[4][4][4] = {};
    gemm_core<14, true>(As, w, g_xh + b * 32768, (l0 - 3) * 64, 64, acc, tid);
    const int wid = tid >> 5, lane = tid & 31, gp = lane >> 2, tg = lane & 3;
#pragma unroll
    for (int nt = 0; nt < 4; nt++) {
        const int f = wid * 32 + nt * 8 + tg * 2;
        const float s0 = g1[f] * rsqrtf(v1[f] + EPSBN);
        const float s1 = g1[f + 1] * rsqrtf(v1[f + 1] + EPSBN);
        const float h0 = (cb[f] - m1[f]) * s0 + b1[f];
        const float h1 = (cb[f + 1] - m1[f + 1]) * s1 + b1[f + 1];
#pragma unroll
        for (int mt = 0; mt < 4; mt++) {
#pragma unroll
            for (int hr = 0; hr < 2; hr++) {
                const int l = l0 + mt * 16 + gp + hr * 8;
                const float y0 = fmaxf(fmaf(acc[mt][nt][hr * 2], s0, h0), 0.f);
                const float y1 = fmaxf(fmaf(acc[mt][nt][hr * 2 + 1], s1, h1), 0.f);
                *(uint2*)&g_yh[(size_t)b * 65536 + (size_t)l * 128 + f] =
                    make_uint2(f2tf(y0), f2tf(y1));
            }
        }
    }
}

// ---------------- Stage 2: LocallyConnected1D(VALID) + BN2 + ReLU ----------------
__global__ __launch_bounds__(128, 4) void local_tc(
    const float* __restrict__ lw, const float* __restrict__ lb,
    const float* __restrict__ g2, const float* __restrict__ b2,
    const float* __restrict__ m2, const float* __restrict__ v2,
    float* __restrict__ out) {
    extern __shared__ uint32_t As[];
    const int tid = threadIdx.x;
    const int l = blockIdx.x;
    float acc[4][4][4] = {};
    gemm_core<28, false>(As, lw + (size_t)l * 896 * 128, g_yh, l * 128, 65536, acc, tid);
    const int wid = tid >> 5, lane = tid & 31, gp = lane >> 2, tg = lane & 3;
#pragma unroll
    for (int nt = 0; nt < 4; nt++) {
        const int f = wid * 32 + nt * 8 + tg * 2;
        const float s0 = g2[f] * rsqrtf(v2[f] + EPSBN);
        const float s1 = g2[f + 1] * rsqrtf(v2[f + 1] + EPSBN);
        const float h0 = (lb[l * 128 + f] - m2[f]) * s0 + b2[f];
        const float h1 = (lb[l * 128 + f + 1] - m2[f + 1]) * s1 + b2[f + 1];
#pragma unroll
        for (int mt = 0; mt < 4; mt++) {
#pragma unroll
            for (int hr = 0; hr < 2; hr++) {
                const int bat = mt * 16 + gp + hr * 8;
                float2 r;
                r.x = fmaxf(fmaf(acc[mt][nt][hr * 2], s0, h0), 0.f);
                r.y = fmaxf(fmaf(acc[mt][nt][hr * 2 + 1], s1, h1), 0.f);
                *(float2*)&out[(size_t)bat * 506 * 128 + (size_t)l * 128 + f] = r;
            }
        }
    }
}

extern "C" void kernel_launch(void* const* d_in, const int* in_sizes, int n_in,
                              void* d_out, int out_size) {
    const float* x      = (const float*)d_in[0];
    const float* conv_w = (const float*)d_in[1];
    const float* conv_b = (const float*)d_in[2];
    const float* g1     = (const float*)d_in[3];
    const float* b1     = (const float*)d_in[4];
    const float* m1     = (const float*)d_in[5];
    const float* v1     = (const float*)d_in[6];
    const float* lw     = (const float*)d_in[7];
    const float* lb     = (const float*)d_in[8];
    const float* g2     = (const float*)d_in[9];
    const float* b2     = (const float*)d_in[10];
    const float* m2     = (const float*)d_in[11];
    const float* v2     = (const float*)d_in[12];
    float* out = (float*)d_out;

    // Idempotent attribute set (host-side, not a stream op -> capture-safe)
    cudaFuncSetAttribute(conv_tc, cudaFuncAttributeMaxDynamicSharedMemorySize, DYNB);
    cudaFuncSetAttribute(local_tc, cudaFuncAttributeMaxDynamicSharedMemorySize, DYNB);

    split_x_kernel<<<2048, 256>>>(x);
    conv_tc<<<dim3(8, 64), 128, DYNB>>>(conv_w, conv_b, g1, b1, m1, v1);
    local_tc<<<506, 128, DYNB>>>(lw, lb, g2, b2, m2, v2, out);
}

// round 8
// speedup vs baseline: 3.9100x; 1.2014x over previous
#include <cuda_runtime.h>
#include <cuda_fp16.h>
#include <cstdint>

#define EPSBN 1e-3f
#define AP2 20                      // A pitch in half2 words
#define AWORDS (64 * AP2)           // 1280 words
#define WPITCH 132
#define WWORDS (32 * WPITCH)        // 4224 words
#define BUFW (AWORDS + WWORDS)      // 5504 words -> 22016 B per buffer

// fp16 activations
__device__ __half g_xh[64 * 512 * 64];
__device__ __half g_yh[64 * 512 * 128];

__device__ __forceinline__ uint32_t s2u(const void* p) {
    uint32_t a;
    asm("{ .reg .u64 t; cvta.to.shared.u64 t, %1; cvt.u32.u64 %0, t; }" : "=r"(a) : "l"(p));
    return a;
}
__device__ __forceinline__ void cpa16(uint32_t d, const void* s, uint32_t sz) {
    asm volatile("cp.async.cg.shared.global [%0], [%1], 16, %2;"
                 :: "r"(d), "l"(s), "r"(sz) : "memory");
}
__device__ __forceinline__ void cpcommit() { asm volatile("cp.async.commit_group;" ::: "memory"); }
template <int N> __device__ __forceinline__ void cpwait() {
    asm volatile("cp.async.wait_group %0;" :: "n"(N) : "memory");
}
__device__ __forceinline__ uint32_t packh2(float lo, float hi) {
    __half2 h = __floats2half2_rn(lo, hi);
    return *(uint32_t*)&h;
}
// m16n8k16 fp16 MMA, fp32 accum
__device__ __forceinline__ void mma16(float* d, const uint32_t* a, const uint32_t* b) {
    asm volatile(
        "mma.sync.aligned.m16n8k16.row.col.f32.f16.f16.f32 "
        "{%0,%1,%2,%3}, {%4,%5,%6,%7}, {%8,%9}, {%0,%1,%2,%3};"
        : "+f"(d[0]), "+f"(d[1]), "+f"(d[2]), "+f"(d[3])
        : "r"(a[0]), "r"(a[1]), "r"(a[2]), "r"(a[3]), "r"(b[0]), "r"(b[1]));
}

// ============================================================================
// GEMM core: D[64 m, 128 f] = half(A)[64, K] * half(W)[K, 128], fp32 accum
// 128 threads = 4 warps; warp w owns f in [w*32, w*32+32) (nt=4).
// A: fp16 elements, row m at element off0 + m*mstride, contiguous along k;
//    staged as half2 words, pitch AP2 (conflict-free fragment LDS).
// W: fp32 [K][128] staged via cp.async (pitch 132), converted to half2 at
//    fragment load. k32 chunks, double-buffered (full-chunk DRAM prefetch).
// CHK: zero-fill A rows outside x (conv SAME padding).
// ============================================================================
template <int NC, bool CHK>
__device__ __forceinline__ void gemm_core(
    uint32_t* As, const float* __restrict__ W, const __half* __restrict__ Ah,
    int off0, int mstride, float acc[4][4][4], int tid) {
    const int w = tid >> 5, lane = tid & 31;
    const int gp = lane >> 2, tg = lane & 3;
    const uint32_t smb = s2u(As);

    auto stage = [&](int c, int buf) {
        const int kc = c * 32;
        const uint32_t bb = smb + (uint32_t)(buf * BUFW) * 4u;
        // A: 4 KB -> 2 cpa/thread (8 halfs each)
#pragma unroll
        for (int q = 0; q < 2; q++) {
            const int idx = tid + 128 * q;
            const int m = idx >> 2, c8 = idx & 3;
            const int so = off0 + m * mstride + kc + c8 * 8;
            const bool ok = !CHK || ((unsigned)so < 32768u);
            cpa16(bb + (uint32_t)(m * AP2 + c8 * 4) * 4u,
                  (const char*)Ah + (size_t)(ok ? so : 0) * 2, ok ? 16u : 0u);
        }
        // W: 16 KB -> 8 cpa/thread
        const uint32_t wb = bb + (uint32_t)AWORDS * 4u;
#pragma unroll
        for (int q = 0; q < 8; q++) {
            const int idx = tid + 128 * q;
            const int row = idx >> 5, c4 = idx & 31;
            cpa16(wb + (uint32_t)(row * WPITCH + c4 * 4) * 4u,
                  W + (size_t)(kc + row) * 128 + c4 * 4, 16u);
        }
        cpcommit();
    };

    stage(0, 0);
    for (int c = 0; c < NC; c++) {
        const int buf = c & 1;
        if (c + 1 < NC) { stage(c + 1, buf ^ 1); cpwait<1>(); }
        else            { cpwait<0>(); }
        __syncthreads();
        const uint32_t* __restrict__ smA = As + buf * BUFW;
        const float* __restrict__ smW = (const float*)(smA + AWORDS);
        const int wcol = w * 32 + gp;
#pragma unroll
        for (int s = 0; s < 2; s++) {  // two k16 steps per k32 chunk
            const float* wp = smW + (s * 16 + tg * 2) * WPITCH + wcol;
            uint32_t b[8];
#pragma unroll
            for (int nt = 0; nt < 4; nt++) {
                b[2 * nt]     = packh2(wp[nt * 8], wp[WPITCH + nt * 8]);
                b[2 * nt + 1] = packh2(wp[8 * WPITCH + nt * 8], wp[9 * WPITCH + nt * 8]);
            }
            const int col = s * 8 + tg;
#pragma unroll
            for (int mt = 0; mt < 4; mt++) {
                const int r = mt * 16 + gp;
                uint32_t a[4];
                a[0] = smA[r * AP2 + col];
                a[1] = smA[(r + 8) * AP2 + col];
                a[2] = smA[r * AP2 + col + 4];
                a[3] = smA[(r + 8) * AP2 + col + 4];
#pragma unroll
                for (int nt = 0; nt < 4; nt++) mma16(acc[mt][nt], a, b + 2 * nt);
            }
        }
        __syncthreads();
    }
}

// ---------------- x -> fp16 ----------------
__global__ __launch_bounds__(256) void split_x_kernel(const float* __restrict__ x) {
    const int i = (blockIdx.x * 256 + threadIdx.x) * 4;
    const float4 v = *(const float4*)&x[i];
    *(uint2*)&g_xh[i] = make_uint2(packh2(v.x, v.y), packh2(v.z, v.w));
}

// ---------------- Stage 1: Conv1D(SAME) + BN1 + ReLU -> g_yh ----------------
__global__ __launch_bounds__(128, 4) void conv_tc(
    const float* __restrict__ w, const float* __restrict__ cb,
    const float* __restrict__ g1, const float* __restrict__ b1,
    const float* __restrict__ m1, const float* __restrict__ v1) {
    __shared__ uint32_t As[2 * BUFW];
    const int tid = threadIdx.x;
    const int b = blockIdx.y, l0 = blockIdx.x * 64;
    float acc[4][4][4] = {};
    gemm_core<14, true>(As, w, g_xh + b * 32768, (l0 - 3) * 64, 64, acc, tid);
    const int wid = tid >> 5, lane = tid & 31, gp = lane >> 2, tg = lane & 3;
#pragma unroll
    for (int nt = 0; nt < 4; nt++) {
        const int f = wid * 32 + nt * 8 + tg * 2;
        const float s0 = g1[f] * rsqrtf(v1[f] + EPSBN);
        const float s1 = g1[f + 1] * rsqrtf(v1[f + 1] + EPSBN);
        const float h0 = (cb[f] - m1[f]) * s0 + b1[f];
        const float h1 = (cb[f + 1] - m1[f + 1]) * s1 + b1[f + 1];
#pragma unroll
        for (int mt = 0; mt < 4; mt++) {
#pragma unroll
            for (int hr = 0; hr < 2; hr++) {
                const int l = l0 + mt * 16 + gp + hr * 8;
                const float y0 = fmaxf(fmaf(acc[mt][nt][hr * 2], s0, h0), 0.f);
                const float y1 = fmaxf(fmaf(acc[mt][nt][hr * 2 + 1], s1, h1), 0.f);
                *(uint32_t*)&g_yh[(size_t)b * 65536 + (size_t)l * 128 + f] = packh2(y0, y1);
            }
        }
    }
}

// ---------------- Stage 2: LocallyConnected1D(VALID) + BN2 + ReLU ----------------
__global__ __launch_bounds__(128, 4) void local_tc(
    const float* __restrict__ lw, const float* __restrict__ lb,
    const float* __restrict__ g2, const float* __restrict__ b2,
    const float* __restrict__ m2, const float* __restrict__ v2,
    float* __restrict__ out) {
    __shared__ uint32_t As[2 * BUFW];
    const int tid = threadIdx.x;
    const int l = blockIdx.x;
    float acc[4][4][4] = {};
    gemm_core<28, false>(As, lw + (size_t)l * 896 * 128, g_yh, l * 128, 65536, acc, tid);
    const int wid = tid >> 5, lane = tid & 31, gp = lane >> 2, tg = lane & 3;
#pragma unroll
    for (int nt = 0; nt < 4; nt++) {
        const int f = wid * 32 + nt * 8 + tg * 2;
        const float s0 = g2[f] * rsqrtf(v2[f] + EPSBN);
        const float s1 = g2[f + 1] * rsqrtf(v2[f + 1] + EPSBN);
        const float h0 = (lb[l * 128 + f] - m2[f]) * s0 + b2[f];
        const float h1 = (lb[l * 128 + f + 1] - m2[f + 1]) * s1 + b2[f + 1];
#pragma unroll
        for (int mt = 0; mt < 4; mt++) {
#pragma unroll
            for (int hr = 0; hr < 2; hr++) {
                const int bat = mt * 16 + gp + hr * 8;
                float2 r;
                r.x = fmaxf(fmaf(acc[mt][nt][hr * 2], s0, h0), 0.f);
                r.y = fmaxf(fmaf(acc[mt][nt][hr * 2 + 1], s1, h1), 0.f);
                *(float2*)&out[(size_t)bat * 506 * 128 + (size_t)l * 128 + f] = r;
            }
        }
    }
}

extern "C" void kernel_launch(void* const* d_in, const int* in_sizes, int n_in,
                              void* d_out, int out_size) {
    const float* x      = (const float*)d_in[0];
    const float* conv_w = (const float*)d_in[1];
    const float* conv_b = (const float*)d_in[2];
    const float* g1     = (const float*)d_in[3];
    const float* b1     = (const float*)d_in[4];
    const float* m1     = (const float*)d_in[5];
    const float* v1     = (const float*)d_in[6];
    const float* lw     = (const float*)d_in[7];
    const float* lb     = (const float*)d_in[8];
    const float* g2     = (const float*)d_in[9];
    const float* b2     = (const float*)d_in[10];
    const float* m2     = (const float*)d_in[11];
    const float* v2     = (const float*)d_in[12];
    float* out = (float*)d_out;

    split_x_kernel<<<2048, 256>>>(x);
    conv_tc<<<dim3(8, 64), 128>>>(conv_w, conv_b, g1, b1, m1, v1);
    local_tc<<<506, 128>>>(lw, lb, g2, b2, m2, v2, out);
}

// round 10
// speedup vs baseline: 4.0177x; 1.0276x over previous
#include <cuda_runtime.h>
#include <cuda_fp16.h>
#include <cstdint>

#define EPSBN 1e-3f
#define AP2 12                       // A pitch in half2 words (k16 chunk: 8 + pad)
#define AWORDS (64 * AP2)            // 768 words
#define WPITCH 132
#define WWORDS (16 * WPITCH)         // 2112 words (k16 chunk of W)
#define BUFW (AWORDS + WWORDS)       // 2880 words = 11520 B
#define NBUF 4                       // 4 buffers, 3 chunks in flight

// fp16 intermediate y
__device__ __half g_yh[64 * 512 * 128];

__device__ __forceinline__ uint32_t s2u(const void* p) {
    uint32_t a;
    asm("{ .reg .u64 t; cvta.to.shared.u64 t, %1; cvt.u32.u64 %0, t; }" : "=r"(a) : "l"(p));
    return a;
}
__device__ __forceinline__ void cpa16(uint32_t d, const void* s, uint32_t sz) {
    asm volatile("cp.async.cg.shared.global [%0], [%1], 16, %2;"
                 :: "r"(d), "l"(s), "r"(sz) : "memory");
}
// evict_first variant for the big streaming W reads (stage 2)
__device__ __forceinline__ void cpa16_ef(uint32_t d, const void* s) {
    asm volatile(
        "{\n\t.reg .b64 pol;\n\t"
        "createpolicy.fractional.L2::evict_first.b64 pol, 1.0;\n\t"
        "cp.async.cg.shared.global.L2::cache_hint [%0], [%1], 16, pol;\n\t}"
        :: "r"(d), "l"(s) : "memory");
}
__device__ __forceinline__ void cpcommit() { asm volatile("cp.async.commit_group;" ::: "memory"); }
template <int N> __device__ __forceinline__ void cpwait() {
    asm volatile("cp.async.wait_group %0;" :: "n"(N) : "memory");
}
__device__ __forceinline__ uint32_t packh2(float lo, float hi) {
    __half2 h = __floats2half2_rn(lo, hi);
    return *(uint32_t*)&h;
}
__device__ __forceinline__ void mma16(float* d, const uint32_t* a, const uint32_t* b) {
    asm volatile(
        "mma.sync.aligned.m16n8k16.row.col.f32.f16.f16.f32 "
        "{%0,%1,%2,%3}, {%4,%5,%6,%7}, {%8,%9}, {%0,%1,%2,%3};"
        : "+f"(d[0]), "+f"(d[1]), "+f"(d[2]), "+f"(d[3])
        : "r"(a[0]), "r"(a[1]), "r"(a[2]), "r"(a[3]), "r"(b[0]), "r"(b[1]));
}

// ============================================================================
// GEMM core: D[64 m, 128 f] = A[64, K] * half(W)[K, 128], fp32 accum.
// 128 threads = 4 warps; warp w owns f in [w*32, w*32+32) (nt=4).
// k16 chunks, 4 buffers, 3 chunks DRAM prefetch in flight.
// Tail-correct waits: wait<3> in steady state, then wait<2>/<1>/<0> for the
// final three iterations (pending count shrinks once staging stops).
// AFP32: A staged from fp32 src via ld+cvt+sts (predicated zero-fill,
//        element index must lie in [0, 32768) -- conv SAME padding).
// else:  A staged from fp16 src via cp.async. W always fp32 via cp.async
//        (EF: evict_first L2 policy), converted to half at fragment load.
// ============================================================================
template <int NC, bool AFP32, bool EF, typename AT>
__device__ __forceinline__ void gemm_core(
    uint32_t* As, const float* __restrict__ W, const AT* __restrict__ Ah,
    int off0, int mstride, float acc[4][4][4], int tid) {
    const int w = tid >> 5, lane = tid & 31;
    const int gp = lane >> 2, tg = lane & 3;
    const uint32_t smb = s2u(As);

    auto stage = [&](int c) {
        const int kc = c * 16;
        const uint32_t bb = smb + (uint32_t)((c & (NBUF - 1)) * BUFW) * 4u;
        if (AFP32) {
            // A: 64 rows x 16 k fp32 -> 2 float4 loads/thread, cvt, sts
#pragma unroll
            for (int q = 0; q < 2; q++) {
                const int idx = tid + 128 * q;
                const int m = idx >> 2, j4 = idx & 3;
                const int e = off0 + m * mstride + kc + j4 * 4;
                float4 v = make_float4(0.f, 0.f, 0.f, 0.f);
                if ((unsigned)e < 32768u) v = *(const float4*)((const float*)Ah + e);
                asm volatile("st.shared.v2.b32 [%0], {%1,%2};"
                             :: "r"(bb + (uint32_t)(m * AP2 + j4 * 2) * 4u),
                                "r"(packh2(v.x, v.y)), "r"(packh2(v.z, v.w)) : "memory");
            }
        } else {
            // A: 64 rows x 16 k fp16 -> 1 cpa16/thread
            const int m = tid >> 1, h = tid & 1;
            const int so = off0 + m * mstride + kc + h * 8;
            cpa16(bb + (uint32_t)(m * AP2 + h * 4) * 4u, (const char*)Ah + (size_t)so * 2, 16u);
        }
        // W: 16 rows x 128 fp32 = 8KB -> 4 cpa16/thread
        const uint32_t wb = bb + (uint32_t)AWORDS * 4u;
#pragma unroll
        for (int q = 0; q < 4; q++) {
            const int idx = tid + 128 * q;
            const int row = idx >> 5, c4 = idx & 31;
            const uint32_t d = wb + (uint32_t)(row * WPITCH + c4 * 4) * 4u;
            const float* s = W + (size_t)(kc + row) * 128 + c4 * 4;
            if (EF) cpa16_ef(d, s); else cpa16(d, s, 16u);
        }
        cpcommit();
    };

    stage(0); stage(1); stage(2);
    for (int c = 0; c < NC; c++) {
        // Stage next chunk and retire chunk c with a pending-count-correct wait.
        if (c + 3 < NC)       { stage(c + 3); cpwait<3>(); }  // pending 4 -> 3
        else if (c + 3 == NC) { cpwait<2>(); }                // pending 3 -> 2
        else if (c + 2 == NC) { cpwait<1>(); }                // pending 2 -> 1
        else                  { cpwait<0>(); }                // pending 1 -> 0
        __syncthreads();
        const uint32_t* __restrict__ smA = As + (c & (NBUF - 1)) * BUFW;
        const float* __restrict__ smW = (const float*)(smA + AWORDS);
        const int wcol = w * 32 + gp;
        const float* wp = smW + tg * 2 * WPITCH + wcol;
        uint32_t b[8];
#pragma unroll
        for (int nt = 0; nt < 4; nt++) {
            b[2 * nt]     = packh2(wp[nt * 8], wp[WPITCH + nt * 8]);
            b[2 * nt + 1] = packh2(wp[8 * WPITCH + nt * 8], wp[9 * WPITCH + nt * 8]);
        }
#pragma unroll
        for (int mt = 0; mt < 4; mt++) {
            const int r = mt * 16 + gp;
            uint32_t a[4];
            a[0] = smA[r * AP2 + tg];
            a[1] = smA[(r + 8) * AP2 + tg];
            a[2] = smA[r * AP2 + tg + 4];
            a[3] = smA[(r + 8) * AP2 + tg + 4];
#pragma unroll
            for (int nt = 0; nt < 4; nt++) mma16(acc[mt][nt], a, b + 2 * nt);
        }
        __syncthreads();
    }
}

// ---------------- Stage 1: Conv1D(SAME) + BN1 + ReLU -> g_yh ----------------
__global__ __launch_bounds__(128, 4) void conv_tc(
    const float* __restrict__ x, const float* __restrict__ w,
    const float* __restrict__ cb,
    const float* __restrict__ g1, const float* __restrict__ b1,
    const float* __restrict__ m1, const float* __restrict__ v1) {
    __shared__ uint32_t As[NBUF * BUFW];
    const int tid = threadIdx.x;
    const int b = blockIdx.y, l0 = blockIdx.x * 64;
    float acc[4][4][4] = {};
    gemm_core<28, true, false>(As, w, x + (size_t)b * 32768, (l0 - 3) * 64, 64, acc, tid);
    const int wid = tid >> 5, lane = tid & 31, gp = lane >> 2, tg = lane & 3;
#pragma unroll
    for (int nt = 0; nt < 4; nt++) {
        const int f = wid * 32 + nt * 8 + tg * 2;
        const float s0 = g1[f] * rsqrtf(v1[f] + EPSBN);
        const float s1 = g1[f + 1] * rsqrtf(v1[f + 1] + EPSBN);
        const float h0 = (cb[f] - m1[f]) * s0 + b1[f];
        const float h1 = (cb[f + 1] - m1[f + 1]) * s1 + b1[f + 1];
#pragma unroll
        for (int mt = 0; mt < 4; mt++) {
#pragma unroll
            for (int hr = 0; hr < 2; hr++) {
                const int l = l0 + mt * 16 + gp + hr * 8;
                const float y0 = fmaxf(fmaf(acc[mt][nt][hr * 2], s0, h0), 0.f);
                const float y1 = fmaxf(fmaf(acc[mt][nt][hr * 2 + 1], s1, h1), 0.f);
                *(uint32_t*)&g_yh[(size_t)b * 65536 + (size_t)l * 128 + f] = packh2(y0, y1);
            }
        }
    }
}

// ---------------- Stage 2: LocallyConnected1D(VALID) + BN2 + ReLU ----------------
__global__ __launch_bounds__(128, 4) void local_tc(
    const float* __restrict__ lw, const float* __restrict__ lb,
    const float* __restrict__ g2, const float* __restrict__ b2,
    const float* __restrict__ m2, const float* __restrict__ v2,
    float* __restrict__ out) {
    __shared__ uint32_t As[NBUF * BUFW];
    const int tid = threadIdx.x;
    const int l = blockIdx.x;
    float acc[4][4][4] = {};
    gemm_core<56, false, true>(As, lw + (size_t)l * 896 * 128, g_yh, l * 128, 65536, acc, tid);
    const int wid = tid >> 5, lane = tid & 31, gp = lane >> 2, tg = lane & 3;
#pragma unroll
    for (int nt = 0; nt < 4; nt++) {
        const int f = wid * 32 + nt * 8 + tg * 2;
        const float s0 = g2[f] * rsqrtf(v2[f] + EPSBN);
        const float s1 = g2[f + 1] * rsqrtf(v2[f + 1] + EPSBN);
        const float h0 = (lb[l * 128 + f] - m2[f]) * s0 + b2[f];
        const float h1 = (lb[l * 128 + f + 1] - m2[f + 1]) * s1 + b2[f + 1];
#pragma unroll
        for (int mt = 0; mt < 4; mt++) {
#pragma unroll
            for (int hr = 0; hr < 2; hr++) {
                const int bat = mt * 16 + gp + hr * 8;
                float2 r;
                r.x = fmaxf(fmaf(acc[mt][nt][hr * 2], s0, h0), 0.f);
                r.y = fmaxf(fmaf(acc[mt][nt][hr * 2 + 1], s1, h1), 0.f);
                *(float2*)&out[(size_t)bat * 506 * 128 + (size_t)l * 128 + f] = r;
            }
        }
    }
}

extern "C" void kernel_launch(void* const* d_in, const int* in_sizes, int n_in,
                              void* d_out, int out_size) {
    const float* x      = (const float*)d_in[0];
    const float* conv_w = (const float*)d_in[1];
    const float* conv_b = (const float*)d_in[2];
    const float* g1     = (const float*)d_in[3];
    const float* b1     = (const float*)d_in[4];
    const float* m1     = (const float*)d_in[5];
    const float* v1     = (const float*)d_in[6];
    const float* lw     = (const float*)d_in[7];
    const float* lb     = (const float*)d_in[8];
    const float* g2     = (const float*)d_in[9];
    const float* b2     = (const float*)d_in[10];
    const float* m2     = (const float*)d_in[11];
    const float* v2     = (const float*)d_in[12];
    float* out = (float*)d_out;

    conv_tc<<<dim3(8, 64), 128>>>(x, conv_w, conv_b, g1, b1, m1, v1);
    local_tc<<<506, 128>>>(lw, lb, g2, b2, m2, v2, out);
}